// round 1
// baseline (speedup 1.0000x reference)
#include <cuda_runtime.h>
#include <math.h>
#include <stdint.h>

#define K_DIM 256
#define MAX_N 1024
#define BM 128
#define BN 128
#define KC 16
#define SROW (BM + 4)   // padded smem row stride (floats)

__device__ float se_g[MAX_N];
__device__ unsigned int counts_g[MAX_N];
__device__ double loss_g;

// ---------------------------------------------------------------------------
// Prep: se[n] = sum_k e[n,k]^2 ; zero counts & loss accumulator.
// One warp per code row. Grid sized so total threads >= max(32*N, MAX_N).
// ---------------------------------------------------------------------------
__global__ void vq_prep(const float* __restrict__ emb, int N) {
    int gtid = blockIdx.x * blockDim.x + threadIdx.x;
    if (gtid < MAX_N) counts_g[gtid] = 0u;
    if (gtid == 0) loss_g = 0.0;
    int w = gtid >> 5;
    int lane = gtid & 31;
    if (w < N) {
        const float4* ep = (const float4*)(emb + (size_t)w * K_DIM);
        float4 a = ep[lane];
        float4 b = ep[lane + 32];
        float s = a.x*a.x + a.y*a.y + a.z*a.z + a.w*a.w
                + b.x*b.x + b.y*b.y + b.z*b.z + b.w*b.w;
        #pragma unroll
        for (int o = 16; o; o >>= 1) s += __shfl_xor_sync(0xffffffffu, s, o);
        if (lane == 0) se_g[w] = s;
    }
}

// ---------------------------------------------------------------------------
// Main fused kernel: fp32 NT-GEMM (f32x2 packed FMA) + argmin + gather +
// straight-through write + loss partial + histogram.
// CTA: 128 rows x all N codes (n-tiles of 128). 256 threads, 8x8 thread tile.
// ---------------------------------------------------------------------------
__global__ __launch_bounds__(256, 2)
void vq_main(const float* __restrict__ x, const float* __restrict__ emb,
             float* __restrict__ out, int M, int N) {
    __shared__ float As[KC][SROW];
    __shared__ float Bs[KC][SROW];
    __shared__ float sxs[BM];
    __shared__ float ses[MAX_N];
    __shared__ unsigned long long keys[BM];

    const int tid  = threadIdx.x;
    const int tx   = tid & 15;
    const int ty   = tid >> 4;
    const int lane = tid & 31;
    const int wid  = tid >> 5;
    const int r0   = blockIdx.x * BM;

    if (tid < BM) keys[tid] = ~0ull;
    for (int i = tid; i < N; i += 256) ses[i] = se_g[i];

    // sx per row (warp wid -> rows wid*16 .. +15)
    for (int rr = 0; rr < 16; rr++) {
        int row = wid * 16 + rr;
        const float4* xp = (const float4*)(x + (size_t)(r0 + row) * K_DIM);
        float4 a = xp[lane];
        float4 b = xp[lane + 32];
        float s = a.x*a.x + a.y*a.y + a.z*a.z + a.w*a.w
                + b.x*b.x + b.y*b.y + b.z*b.z + b.w*b.w;
        #pragma unroll
        for (int o = 16; o; o >>= 1) s += __shfl_xor_sync(0xffffffffu, s, o);
        if (lane == 0) sxs[row] = s;
    }
    __syncthreads();

    float bestV[8];
    int   bestI[8];
    #pragma unroll
    for (int i = 0; i < 8; i++) { bestV[i] = 3.4e38f; bestI[i] = 0; }

    const int ntiles = N / BN;
    for (int nt = 0; nt < ntiles; nt++) {
        const int n0 = nt * BN;
        unsigned long long acc[8][4];   // 8 rows x 4 col-pairs, packed f32x2
        #pragma unroll
        for (int i = 0; i < 8; i++)
            #pragma unroll
            for (int j = 0; j < 4; j++) acc[i][j] = 0ull;

        for (int kc = 0; kc < K_DIM / KC; kc++) {
            const int k0 = kc * KC;
            // stage A (x tile, transposed) and B (codes tile, transposed)
            #pragma unroll
            for (int p = 0; p < (BM * KC) / 256; p++) {
                int idx = tid + p * 256;
                int kk  = idx & (KC - 1);
                int row = idx >> 4;
                As[kk][row] = x[(size_t)(r0 + row) * K_DIM + k0 + kk];
            }
            #pragma unroll
            for (int p = 0; p < (BN * KC) / 256; p++) {
                int idx = tid + p * 256;
                int kk  = idx & (KC - 1);
                int col = idx >> 4;
                Bs[kk][col] = emb[(size_t)(n0 + col) * K_DIM + k0 + kk];
            }
            __syncthreads();

            #pragma unroll
            for (int k = 0; k < KC; k++) {
                float4 a0 = *(const float4*)&As[k][ty * 4];
                float4 a1 = *(const float4*)&As[k][ty * 4 + 64];
                ulonglong2 b0 = *(const ulonglong2*)&Bs[k][tx * 4];
                ulonglong2 b1 = *(const ulonglong2*)&Bs[k][tx * 4 + 64];
                float av[8] = {a0.x, a0.y, a0.z, a0.w, a1.x, a1.y, a1.z, a1.w};
                unsigned long long bp[4] = {b0.x, b0.y, b1.x, b1.y};
                #pragma unroll
                for (int i = 0; i < 8; i++) {
                    unsigned long long ap;
                    asm("mov.b64 %0, {%1, %1};" : "=l"(ap) : "f"(av[i]));
                    #pragma unroll
                    for (int j = 0; j < 4; j++) {
                        asm("fma.rn.f32x2 %0, %1, %2, %0;"
                            : "+l"(acc[i][j]) : "l"(ap), "l"(bp[j]));
                    }
                }
            }
            __syncthreads();
        }

        // scores + running argmin (ascending col order => first-min tiebreak)
        #pragma unroll
        for (int i = 0; i < 8; i++) {
            int row = (i < 4) ? (ty * 4 + i) : (64 + ty * 4 + (i - 4));
            float sx = sxs[row];
            #pragma unroll
            for (int j = 0; j < 4; j++) {
                float d0, d1;
                asm("mov.b64 {%0, %1}, %2;" : "=f"(d0), "=f"(d1) : "l"(acc[i][j]));
                int cbase = (j < 2) ? (tx * 4 + j * 2) : (64 + tx * 4 + (j - 2) * 2);
                int c0 = n0 + cbase;
                float s0 = fmaf(-2.0f, d0, sx + ses[c0]);
                float s1 = fmaf(-2.0f, d1, sx + ses[c0 + 1]);
                if (s0 < bestV[i]) { bestV[i] = s0; bestI[i] = c0; }
                if (s1 < bestV[i]) { bestV[i] = s1; bestI[i] = c0 + 1; }
            }
        }
    }

    // cross-thread argmin merge: 64-bit key = ordered(score) || idx
    #pragma unroll
    for (int i = 0; i < 8; i++) {
        int row = (i < 4) ? (ty * 4 + i) : (64 + ty * 4 + (i - 4));
        unsigned int fb = __float_as_uint(bestV[i]);
        fb = (fb & 0x80000000u) ? ~fb : (fb | 0x80000000u);
        unsigned long long key =
            ((unsigned long long)fb << 32) | (unsigned int)bestI[i];
        atomicMin(&keys[row], key);
    }
    __syncthreads();

    // epilogue: gather e[idx], write qst = x + (q - x), loss partial, histogram
    float wsum = 0.0f;
    for (int rr = 0; rr < 16; rr++) {
        int row = wid * 16 + rr;
        int gr  = r0 + row;
        unsigned int idx = (unsigned int)(keys[row] & 0xffffffffu);
        const float4* ep = (const float4*)(emb + (size_t)idx * K_DIM);
        const float4* xp = (const float4*)(x + (size_t)gr * K_DIM);
        float4*       op = (float4*)(out + (size_t)gr * K_DIM);
        #pragma unroll
        for (int t = 0; t < 2; t++) {
            int j = lane + t * 32;
            float4 q  = ep[j];
            float4 xv = xp[j];
            float dx = q.x - xv.x, dy = q.y - xv.y;
            float dz = q.z - xv.z, dw = q.w - xv.w;
            float4 o;
            o.x = xv.x + dx; o.y = xv.y + dy;
            o.z = xv.z + dz; o.w = xv.w + dw;
            op[j] = o;
            wsum += dx*dx + dy*dy + dz*dz + dw*dw;
        }
        if (lane == 0) atomicAdd(&counts_g[idx], 1u);
    }
    #pragma unroll
    for (int o = 16; o; o >>= 1) wsum += __shfl_xor_sync(0xffffffffu, wsum, o);
    if (lane == 0) atomicAdd(&loss_g, (double)wsum);
}

// ---------------------------------------------------------------------------
// Finalize: loss = 1.25 * mean((q-x)^2) ; perplexity = exp(-sum p log(p+1e-10))
// ---------------------------------------------------------------------------
__global__ void vq_finalize(float* __restrict__ out, long long ME, int M, int N,
                            int write_scalars) {
    __shared__ float red[32];
    int tid = threadIdx.x;
    float v = 0.0f;
    if (tid < N) {
        float p = (float)counts_g[tid] / (float)M;
        v = p * logf(p + 1e-10f);
    }
    #pragma unroll
    for (int o = 16; o; o >>= 1) v += __shfl_xor_sync(0xffffffffu, v, o);
    if ((tid & 31) == 0) red[tid >> 5] = v;
    __syncthreads();
    if (tid < 32) {
        float s = (tid < ((int)blockDim.x >> 5)) ? red[tid] : 0.0f;
        #pragma unroll
        for (int o = 16; o; o >>= 1) s += __shfl_xor_sync(0xffffffffu, s, o);
        if (tid == 0 && write_scalars) {
            float perp = expf(-s);
            float m = (float)(loss_g / (double)ME);
            float loss = m + 0.25f * m;
            out[ME]     = loss;
            out[ME + 1] = perp;
        }
    }
}

// ---------------------------------------------------------------------------
extern "C" void kernel_launch(void* const* d_in, const int* in_sizes, int n_in,
                              void* d_out, int out_size) {
    const float* x   = (const float*)d_in[0];
    const float* emb = (const float*)d_in[1];
    float* out = (float*)d_out;

    int M = in_sizes[0] / K_DIM;   // 65536
    int N = in_sizes[1] / K_DIM;   // 1024

    int prep_threads = N * 32;
    if (prep_threads < MAX_N) prep_threads = MAX_N;
    vq_prep<<<(prep_threads + 255) / 256, 256>>>(emb, N);

    vq_main<<<M / BM, 256>>>(x, emb, out, M, N);

    long long ME = (long long)M * K_DIM;
    int ws = ((long long)out_size >= ME + 2) ? 1 : 0;
    vq_finalize<<<1, 1024>>>(out, ME, M, N, ws);
}

// round 3
// speedup vs baseline: 1.1641x; 1.1641x over previous
#include <cuda_runtime.h>
#include <math.h>
#include <stdint.h>

#define K_DIM 256
#define MAX_N 1024
#define BM 128
#define ROWF 260                    // padded floats per smem row
#define ROWB (ROWF * 4)             // 1040 bytes
#define A_BYTES (BM * ROWB)         // 133120
#define B_COLS 64
#define B_BYTES (B_COLS * ROWB)     // 66560

#define A_OFF   0
#define B_OFF   A_BYTES
#define SES_OFF (A_BYTES + B_BYTES)       // 199680
#define SXS_OFF (SES_OFF + MAX_N * 4)     // 203776
#define KEYS_OFF (SXS_OFF + BM * 4)       // 204288
#define SMEM_TOTAL (KEYS_OFF + BM * 8)    // 205312

__device__ float se_g[MAX_N];
__device__ unsigned int counts_g[MAX_N];
__device__ double loss_g;

__device__ __forceinline__ uint32_t smem_u32(const void* p) {
    uint32_t a;
    asm("{ .reg .u64 t; cvta.to.shared.u64 t, %1; cvt.u32.u64 %0, t; }"
        : "=r"(a) : "l"(p));
    return a;
}
__device__ __forceinline__ void cpa16(uint32_t s, const void* g) {
    asm volatile("cp.async.cg.shared.global [%0], [%1], 16;" :: "r"(s), "l"(g));
}
__device__ __forceinline__ void cpa_commit() {
    asm volatile("cp.async.commit_group;" ::: "memory");
}
__device__ __forceinline__ void cpa_wait0() {
    asm volatile("cp.async.wait_group 0;" ::: "memory");
}
__device__ __forceinline__ void mma_tf32(float& d0, float& d1, float& d2, float& d3,
                                         uint32_t a0, uint32_t a1, uint32_t a2, uint32_t a3,
                                         uint32_t b0, uint32_t b1) {
    asm volatile("mma.sync.aligned.m16n8k8.row.col.f32.tf32.tf32.f32 "
                 "{%0,%1,%2,%3},{%4,%5,%6,%7},{%8,%9},{%0,%1,%2,%3};"
                 : "+f"(d0), "+f"(d1), "+f"(d2), "+f"(d3)
                 : "r"(a0), "r"(a1), "r"(a2), "r"(a3), "r"(b0), "r"(b1));
}

// ---------------------------------------------------------------------------
__global__ void vq_prep(const float* __restrict__ emb, int N) {
    int gtid = blockIdx.x * blockDim.x + threadIdx.x;
    if (gtid < MAX_N) counts_g[gtid] = 0u;
    if (gtid == 0) loss_g = 0.0;
    int w = gtid >> 5, lane = gtid & 31;
    if (w < N) {
        const float4* ep = (const float4*)(emb + (size_t)w * K_DIM);
        float4 a = ep[lane];
        float4 b = ep[lane + 32];
        float s = a.x*a.x + a.y*a.y + a.z*a.z + a.w*a.w
                + b.x*b.x + b.y*b.y + b.z*b.z + b.w*b.w;
        #pragma unroll
        for (int o = 16; o; o >>= 1) s += __shfl_xor_sync(0xffffffffu, s, o);
        if (lane == 0) se_g[w] = s;
    }
}

// ---------------------------------------------------------------------------
// Main: tf32 mma.sync coarse GEMM + per-thread top-3 + exact fp32 rescore +
// gather + straight-through write + loss + histogram.
// ---------------------------------------------------------------------------
__global__ __launch_bounds__(256, 1)
void vq_main(const float* __restrict__ x, const float* __restrict__ emb,
             float* __restrict__ out, int M, int N) {
    extern __shared__ char sm[];
    float* As  = (float*)(sm + A_OFF);
    float* Bs  = (float*)(sm + B_OFF);
    float* ses = (float*)(sm + SES_OFF);
    float* sxs = (float*)(sm + SXS_OFF);
    unsigned long long* keys = (unsigned long long*)(sm + KEYS_OFF);

    const uint32_t sb = smem_u32(sm);
    const int tid  = threadIdx.x;
    const int lane = tid & 31;
    const int wid  = tid >> 5;
    const int tg   = lane >> 2;      // group id 0..7
    const int tq   = lane & 3;       // thread-in-group
    const int r0   = blockIdx.x * BM;
    const int row0 = wid * 16 + tg;  // first owned row (CTA-local)
    const int row1 = row0 + 8;

    // ---- stage A tile (exact fp32) via cp.async: 2 threads per row ----
    {
        int arow = tid >> 1;
        int half = tid & 1;
        const char* src = (const char*)(x + (size_t)(r0 + arow) * K_DIM + half * 128);
        uint32_t dst = sb + A_OFF + arow * ROWB + half * 512;
        #pragma unroll
        for (int i = 0; i < 32; i++) cpa16(dst + i * 16, src + i * 16);
    }
    cpa_commit();
    if (tid < BM) keys[tid] = ~0ull;
    for (int i = tid; i < N; i += 256) ses[i] = se_g[i];
    cpa_wait0();
    __syncthreads();

    // ---- sx per row (round-1 recipe, reading exact A from smem) ----
    for (int rr = 0; rr < 16; rr++) {
        int row = wid * 16 + rr;
        const float4* xp = (const float4*)(As + row * ROWF);
        float4 a = xp[lane];
        float4 b = xp[lane + 32];
        float s = a.x*a.x + a.y*a.y + a.z*a.z + a.w*a.w
                + b.x*b.x + b.y*b.y + b.z*b.z + b.w*b.w;
        #pragma unroll
        for (int o = 16; o; o >>= 1) s += __shfl_xor_sync(0xffffffffu, s, o);
        if (lane == 0) sxs[row] = s;
    }
    __syncthreads();

    float sxr[2] = {sxs[row0], sxs[row1]};

    float v[2][3] = {{3.4e38f, 3.4e38f, 3.4e38f}, {3.4e38f, 3.4e38f, 3.4e38f}};
    int   ix[2][3] = {{0, 0, 0}, {0, 0, 0}};

    const float* Ap = As + row0 * ROWF + tq;   // A frag base (rows row0/row1)
    const float* Bp = Bs + tg * ROWF + tq;     // B frag base (col tg within tile)

    const int nchunks = N / B_COLS;
    for (int nt = 0; nt < nchunks; nt++) {
        // ---- stage B chunk: 64 cols x 256 k (raw fp32; tf32 by truncation) ----
        {
            int col = tid >> 2, q = tid & 3;
            const char* src = (const char*)(emb + (size_t)(nt * B_COLS + col) * K_DIM + q * 64);
            uint32_t dst = sb + B_OFF + col * ROWB + q * 256;
            #pragma unroll
            for (int i = 0; i < 16; i++) cpa16(dst + i * 16, src + i * 16);
        }
        cpa_commit();
        cpa_wait0();
        __syncthreads();

        float acc[32];
        #pragma unroll
        for (int i = 0; i < 32; i++) acc[i] = 0.0f;

        #pragma unroll 4
        for (int s = 0; s < 32; s++) {
            uint32_t a0 = __float_as_uint(Ap[s * 8]);
            uint32_t a2 = __float_as_uint(Ap[s * 8 + 4]);
            uint32_t a1 = __float_as_uint(Ap[8 * ROWF + s * 8]);
            uint32_t a3 = __float_as_uint(Ap[8 * ROWF + s * 8 + 4]);
            #pragma unroll
            for (int j = 0; j < 8; j++) {
                uint32_t b0 = __float_as_uint(Bp[j * 8 * ROWF + s * 8]);
                uint32_t b1 = __float_as_uint(Bp[j * 8 * ROWF + s * 8 + 4]);
                mma_tf32(acc[j*4+0], acc[j*4+1], acc[j*4+2], acc[j*4+3],
                         a0, a1, a2, a3, b0, b1);
            }
        }
        __syncthreads();   // all warps done reading Bs before next staging

        // ---- coarse scores -> top-3 per (thread,row), ascending col order ----
        #pragma unroll
        for (int j = 0; j < 8; j++) {
            #pragma unroll
            for (int c = 0; c < 4; c++) {
                const int rs = c >> 1;
                int col = nt * B_COLS + j * 8 + tq * 2 + (c & 1);
                float s = fmaf(-2.0f, acc[j * 4 + c], sxr[rs] + ses[col]);
                if (s < v[rs][2]) {
                    if (s < v[rs][1]) {
                        if (s < v[rs][0]) {
                            v[rs][2] = v[rs][1]; ix[rs][2] = ix[rs][1];
                            v[rs][1] = v[rs][0]; ix[rs][1] = ix[rs][0];
                            v[rs][0] = s;        ix[rs][0] = col;
                        } else {
                            v[rs][2] = v[rs][1]; ix[rs][2] = ix[rs][1];
                            v[rs][1] = s;        ix[rs][1] = col;
                        }
                    } else { v[rs][2] = s; ix[rs][2] = col; }
                }
            }
        }
    }

    // ---- exact fp32 rescore of candidates (x exact from smem A) ----
    #pragma unroll
    for (int rs = 0; rs < 2; rs++) {
        int row = (rs == 0) ? row0 : row1;
        const float4* xp4 = (const float4*)(As + row * ROWF);
        #pragma unroll
        for (int cnd = 0; cnd < 3; cnd++) {
            int ci = ix[rs][cnd];
            const float4* ep = (const float4*)(emb + (size_t)ci * K_DIM);
            float dot = 0.0f;
            #pragma unroll 8
            for (int q = 0; q < 64; q++) {
                float4 e4 = __ldg(ep + q);
                float4 x4 = xp4[q];
                dot = fmaf(x4.x, e4.x, dot);
                dot = fmaf(x4.y, e4.y, dot);
                dot = fmaf(x4.z, e4.z, dot);
                dot = fmaf(x4.w, e4.w, dot);
            }
            float s = fmaf(-2.0f, dot, sxr[rs] + ses[ci]);
            unsigned int fb = __float_as_uint(s);
            fb = (fb & 0x80000000u) ? ~fb : (fb | 0x80000000u);
            atomicMin(&keys[row], ((unsigned long long)fb << 32) | (unsigned int)ci);
        }
    }
    __syncthreads();

    // ---- epilogue (round-1 recipe; x read exact from smem A) ----
    float wsum = 0.0f;
    for (int rr = 0; rr < 16; rr++) {
        int row = wid * 16 + rr;
        int gr  = r0 + row;
        unsigned int idx = (unsigned int)(keys[row] & 0xffffffffu);
        const float4* ep = (const float4*)(emb + (size_t)idx * K_DIM);
        const float4* xp = (const float4*)(As + row * ROWF);
        float4*       op = (float4*)(out + (size_t)gr * K_DIM);
        #pragma unroll
        for (int t = 0; t < 2; t++) {
            int j = lane + t * 32;
            float4 q  = __ldg(ep + j);
            float4 xv = xp[j];
            float dx = q.x - xv.x, dy = q.y - xv.y;
            float dz = q.z - xv.z, dw = q.w - xv.w;
            float4 o;
            o.x = xv.x + dx; o.y = xv.y + dy;
            o.z = xv.z + dz; o.w = xv.w + dw;
            op[j] = o;
            wsum += dx*dx + dy*dy + dz*dz + dw*dw;
        }
        if (lane == 0) atomicAdd(&counts_g[idx], 1u);
    }
    #pragma unroll
    for (int o = 16; o; o >>= 1) wsum += __shfl_xor_sync(0xffffffffu, wsum, o);
    if (lane == 0) atomicAdd(&loss_g, (double)wsum);
}

// ---------------------------------------------------------------------------
__global__ void vq_finalize(float* __restrict__ out, long long ME, int M, int N,
                            int write_scalars) {
    __shared__ float red[32];
    int tid = threadIdx.x;
    float v = 0.0f;
    if (tid < N) {
        float p = (float)counts_g[tid] / (float)M;
        v = p * logf(p + 1e-10f);
    }
    #pragma unroll
    for (int o = 16; o; o >>= 1) v += __shfl_xor_sync(0xffffffffu, v, o);
    if ((tid & 31) == 0) red[tid >> 5] = v;
    __syncthreads();
    if (tid < 32) {
        float s = (tid < ((int)blockDim.x >> 5)) ? red[tid] : 0.0f;
        #pragma unroll
        for (int o = 16; o; o >>= 1) s += __shfl_xor_sync(0xffffffffu, s, o);
        if (tid == 0 && write_scalars) {
            float perp = expf(-s);
            float m = (float)(loss_g / (double)ME);
            out[ME]     = m + 0.25f * m;
            out[ME + 1] = perp;
        }
    }
}

// ---------------------------------------------------------------------------
extern "C" void kernel_launch(void* const* d_in, const int* in_sizes, int n_in,
                              void* d_out, int out_size) {
    const float* x   = (const float*)d_in[0];
    const float* emb = (const float*)d_in[1];
    float* out = (float*)d_out;

    int M = in_sizes[0] / K_DIM;   // 65536
    int N = in_sizes[1] / K_DIM;   // 1024

    static int smem_set = 0;
    if (!smem_set) {
        cudaFuncSetAttribute(vq_main, cudaFuncAttributeMaxDynamicSharedMemorySize,
                             SMEM_TOTAL);
        smem_set = 1;
    }

    int prep_threads = N * 32;
    if (prep_threads < MAX_N) prep_threads = MAX_N;
    vq_prep<<<(prep_threads + 255) / 256, 256>>>(emb, N);

    vq_main<<<M / BM, 256, SMEM_TOTAL>>>(x, emb, out, M, N);

    long long ME = (long long)M * K_DIM;
    int ws = ((long long)out_size >= ME + 2) ? 1 : 0;
    vq_finalize<<<1, 1024>>>(out, ME, M, N, ws);
}

// round 4
// speedup vs baseline: 1.4753x; 1.2673x over previous
#include <cuda_runtime.h>
#include <cuda_bf16.h>
#include <math.h>
#include <stdint.h>

#define K_DIM 256
#define MAX_N 1024
#define BM 128
#define AROWB 528                     // bf16 row stride bytes (33 x 16B, odd -> conflict-free)
#define A_OFF 0
#define A_BYTES (BM * AROWB)          // 67584
#define B_BYTES (64 * AROWB)          // 33792 per buffer
#define B0_OFF A_BYTES
#define B1_OFF (A_BYTES + B_BYTES)
#define SES_OFF (A_BYTES + 2 * B_BYTES)       // 135168
#define SXS_OFF (SES_OFF + MAX_N * 4)         // 139264
#define KEYS_OFF (SXS_OFF + BM * 4)           // 139776
#define SMEM_TOTAL (KEYS_OFF + BM * 8)        // 140800

__device__ float se_g[MAX_N];
__device__ unsigned int counts_g[MAX_N];
__device__ double loss_g;
__device__ __align__(16) uint16_t emb_bf16_g[MAX_N * K_DIM];

__device__ __forceinline__ uint32_t smem_u32(const void* p) {
    uint32_t a;
    asm("{ .reg .u64 t; cvta.to.shared.u64 t, %1; cvt.u32.u64 %0, t; }"
        : "=r"(a) : "l"(p));
    return a;
}
__device__ __forceinline__ void cpa16(uint32_t s, const void* g) {
    asm volatile("cp.async.cg.shared.global [%0], [%1], 16;" :: "r"(s), "l"(g));
}
__device__ __forceinline__ void cpa_commit() {
    asm volatile("cp.async.commit_group;" ::: "memory");
}
__device__ __forceinline__ void cpa_wait0() {
    asm volatile("cp.async.wait_group 0;" ::: "memory");
}
__device__ __forceinline__ void cpa_wait1() {
    asm volatile("cp.async.wait_group 1;" ::: "memory");
}
__device__ __forceinline__ void ldm_x4(uint32_t& r0, uint32_t& r1, uint32_t& r2,
                                       uint32_t& r3, uint32_t a) {
    asm volatile("ldmatrix.sync.aligned.m8n8.x4.shared.b16 {%0,%1,%2,%3}, [%4];"
                 : "=r"(r0), "=r"(r1), "=r"(r2), "=r"(r3) : "r"(a));
}
__device__ __forceinline__ void mma_bf16(float& d0, float& d1, float& d2, float& d3,
                                         uint32_t a0, uint32_t a1, uint32_t a2, uint32_t a3,
                                         uint32_t b0, uint32_t b1) {
    asm volatile("mma.sync.aligned.m16n8k16.row.col.f32.bf16.bf16.f32 "
                 "{%0,%1,%2,%3},{%4,%5,%6,%7},{%8,%9},{%0,%1,%2,%3};"
                 : "+f"(d0), "+f"(d1), "+f"(d2), "+f"(d3)
                 : "r"(a0), "r"(a1), "r"(a2), "r"(a3), "r"(b0), "r"(b1));
}
__device__ __forceinline__ uint32_t f2bf2(float lo, float hi) {
    __nv_bfloat162 h = __float22bfloat162_rn(make_float2(lo, hi));
    return *(uint32_t*)&h;
}

__global__ void vq_nop() {}

// ---------------------------------------------------------------------------
// Prep: se[n], emb -> bf16 copy, zero counts & loss. One warp per code row.
// ---------------------------------------------------------------------------
__global__ void vq_prep(const float* __restrict__ emb, int N) {
    int gtid = blockIdx.x * blockDim.x + threadIdx.x;
    if (gtid < MAX_N) counts_g[gtid] = 0u;
    if (gtid == 0) loss_g = 0.0;
    int w = gtid >> 5, lane = gtid & 31;
    if (w < N) {
        const float4* ep = (const float4*)(emb + (size_t)w * K_DIM);
        float4 a = ep[lane];
        float4 b = ep[lane + 32];
        float s = a.x*a.x + a.y*a.y + a.z*a.z + a.w*a.w
                + b.x*b.x + b.y*b.y + b.z*b.z + b.w*b.w;
        uint32_t* bp = (uint32_t*)(emb_bf16_g + (size_t)w * K_DIM);
        bp[lane * 2]          = f2bf2(a.x, a.y);
        bp[lane * 2 + 1]      = f2bf2(a.z, a.w);
        bp[64 + lane * 2]     = f2bf2(b.x, b.y);
        bp[64 + lane * 2 + 1] = f2bf2(b.z, b.w);
        #pragma unroll
        for (int o = 16; o; o >>= 1) s += __shfl_xor_sync(0xffffffffu, s, o);
        if (lane == 0) se_g[w] = s;
    }
}

// ---------------------------------------------------------------------------
// Main: bf16 mma.sync (ldmatrix-fed, double-buffered B) coarse GEMM +
// per-thread top-3 + exact fp32 rescore + gather + ST write + loss + hist.
// ---------------------------------------------------------------------------
__global__ __launch_bounds__(256)
void vq_main(const float* __restrict__ x, const float* __restrict__ emb,
             float* __restrict__ out, int M, int N) {
    extern __shared__ char sm[];
    float* ses = (float*)(sm + SES_OFF);
    float* sxs = (float*)(sm + SXS_OFF);
    unsigned long long* keys = (unsigned long long*)(sm + KEYS_OFF);

    const uint32_t sb = smem_u32(sm);
    const int tid  = threadIdx.x;
    const int lane = tid & 31;
    const int wid  = tid >> 5;
    const int tg   = lane >> 2;
    const int tq   = lane & 3;
    const int r0   = blockIdx.x * BM;
    const int row0 = wid * 16 + tg;
    const int row1 = row0 + 8;

    const uint32_t boff[2] = {B0_OFF, B1_OFF};

    // ---- prefetch B chunk 0 (bf16 from emb_bf16_g) ----
    {
        int col = tid >> 2, part = tid & 3;
        const char* src = (const char*)emb_bf16_g + (size_t)col * 512 + part * 128;
        uint32_t dst = sb + B0_OFF + col * AROWB + part * 128;
        #pragma unroll
        for (int i = 0; i < 8; i++) cpa16(dst + i * 16, src + i * 16);
    }
    cpa_commit();

    // ---- stage A tile as bf16 (converted from fp32 gmem) ----
    {
        int arow = tid >> 1, half = tid & 1;
        const float4* xp4 = (const float4*)(x + (size_t)(r0 + arow) * K_DIM) + half * 32;
        uint32_t dst = sb + A_OFF + arow * AROWB + half * 256;
        #pragma unroll
        for (int i = 0; i < 16; i++) {
            float4 fa = __ldg(xp4 + 2 * i);
            float4 fb = __ldg(xp4 + 2 * i + 1);
            uint4 u;
            u.x = f2bf2(fa.x, fa.y);
            u.y = f2bf2(fa.z, fa.w);
            u.z = f2bf2(fb.x, fb.y);
            u.w = f2bf2(fb.z, fb.w);
            *(uint4*)(sm + (dst - sb) + i * 16) = u;
        }
    }

    if (tid < BM) keys[tid] = ~0ull;
    for (int i = tid; i < N; i += 256) ses[i] = se_g[i];

    // ---- sx per row: EXACT round-1 recipe (gmem float4 + shfl tree) ----
    for (int rr = 0; rr < 16; rr++) {
        int row = wid * 16 + rr;
        const float4* xp = (const float4*)(x + (size_t)(r0 + row) * K_DIM);
        float4 a = xp[lane];
        float4 b = xp[lane + 32];
        float s = a.x*a.x + a.y*a.y + a.z*a.z + a.w*a.w
                + b.x*b.x + b.y*b.y + b.z*b.z + b.w*b.w;
        #pragma unroll
        for (int o = 16; o; o >>= 1) s += __shfl_xor_sync(0xffffffffu, s, o);
        if (lane == 0) sxs[row] = s;
    }

    // per-lane ldmatrix base offsets
    const uint32_t aBase = sb + A_OFF + (uint32_t)(row0 - tg + (lane & 15)) * AROWB
                         + (uint32_t)(lane >> 4) * 16;
    const uint32_t bLane = (uint32_t)((((lane >> 4) << 3) + (lane & 7))) * AROWB
                         + (uint32_t)((lane >> 3) & 1) * 16;

    float v[2][3] = {{3.4e38f, 3.4e38f, 3.4e38f}, {3.4e38f, 3.4e38f, 3.4e38f}};
    int   ix[2][3] = {{0, 0, 0}, {0, 0, 0}};

    for (int nt = 0; nt < 16; nt++) {
        const int cur = nt & 1;
        // prefetch next chunk into the other buffer
        if (nt + 1 < 16) {
            int col = tid >> 2, part = tid & 3;
            const char* src = (const char*)emb_bf16_g
                            + (size_t)(nt + 1) * 64 * 512 + (size_t)col * 512 + part * 128;
            uint32_t dst = sb + boff[cur ^ 1] + col * AROWB + part * 128;
            #pragma unroll
            for (int i = 0; i < 8; i++) cpa16(dst + i * 16, src + i * 16);
            cpa_commit();
            cpa_wait1();
        } else {
            cpa_wait0();
        }
        __syncthreads();   // cur buffer visible to all

        float acc[8][4];
        #pragma unroll
        for (int b = 0; b < 8; b++)
            #pragma unroll
            for (int c = 0; c < 4; c++) acc[b][c] = 0.0f;

        const uint32_t bBase = sb + boff[cur] + bLane;
        #pragma unroll
        for (int ks = 0; ks < 16; ks++) {
            uint32_t a0, a1, a2, a3;
            ldm_x4(a0, a1, a2, a3, aBase + ks * 32);
            #pragma unroll
            for (int jj = 0; jj < 4; jj++) {
                uint32_t b0, b1, b2, b3;
                ldm_x4(b0, b1, b2, b3, bBase + jj * (16 * AROWB) + ks * 32);
                mma_bf16(acc[2*jj][0], acc[2*jj][1], acc[2*jj][2], acc[2*jj][3],
                         a0, a1, a2, a3, b0, b1);
                mma_bf16(acc[2*jj+1][0], acc[2*jj+1][1], acc[2*jj+1][2], acc[2*jj+1][3],
                         a0, a1, a2, a3, b2, b3);
            }
        }
        __syncthreads();   // all reads of cur done before it is overwritten

        // coarse scores -> top-3 per (thread,row-slot), ascending col order
        #pragma unroll
        for (int b = 0; b < 8; b++) {
            #pragma unroll
            for (int c = 0; c < 4; c++) {
                const int rs = c >> 1;
                int col = nt * 64 + b * 8 + tq * 2 + (c & 1);
                float s = fmaf(-2.0f, acc[b][c], ses[col]);
                if (s < v[rs][2]) {
                    if (s < v[rs][1]) {
                        if (s < v[rs][0]) {
                            v[rs][2] = v[rs][1]; ix[rs][2] = ix[rs][1];
                            v[rs][1] = v[rs][0]; ix[rs][1] = ix[rs][0];
                            v[rs][0] = s;        ix[rs][0] = col;
                        } else {
                            v[rs][2] = v[rs][1]; ix[rs][2] = ix[rs][1];
                            v[rs][1] = s;        ix[rs][1] = col;
                        }
                    } else { v[rs][2] = s; ix[rs][2] = col; }
                }
            }
        }
    }

    // ---- exact fp32 rescore of candidates (round-1 scoring chain) ----
    #pragma unroll
    for (int rs = 0; rs < 2; rs++) {
        int row = (rs == 0) ? row0 : row1;
        float sx = sxs[row];
        const float4* xp4 = (const float4*)(x + (size_t)(r0 + row) * K_DIM);
        #pragma unroll
        for (int cnd = 0; cnd < 3; cnd++) {
            int ci = ix[rs][cnd];
            const float4* ep = (const float4*)(emb + (size_t)ci * K_DIM);
            float dot = 0.0f;
            #pragma unroll 8
            for (int q = 0; q < 64; q++) {
                float4 e4 = __ldg(ep + q);
                float4 x4 = __ldg(xp4 + q);
                dot = fmaf(x4.x, e4.x, dot);
                dot = fmaf(x4.y, e4.y, dot);
                dot = fmaf(x4.z, e4.z, dot);
                dot = fmaf(x4.w, e4.w, dot);
            }
            float s = fmaf(-2.0f, dot, sx + ses[ci]);
            unsigned int fb = __float_as_uint(s);
            fb = (fb & 0x80000000u) ? ~fb : (fb | 0x80000000u);
            atomicMin(&keys[row], ((unsigned long long)fb << 32) | (unsigned int)ci);
        }
    }
    __syncthreads();

    // ---- epilogue (round-1 recipe, x from gmem) ----
    float wsum = 0.0f;
    for (int rr = 0; rr < 16; rr++) {
        int row = wid * 16 + rr;
        int gr  = r0 + row;
        unsigned int idx = (unsigned int)(keys[row] & 0xffffffffu);
        const float4* ep = (const float4*)(emb + (size_t)idx * K_DIM);
        const float4* xp = (const float4*)(x + (size_t)gr * K_DIM);
        float4*       op = (float4*)(out + (size_t)gr * K_DIM);
        #pragma unroll
        for (int t = 0; t < 2; t++) {
            int j = lane + t * 32;
            float4 q  = __ldg(ep + j);
            float4 xv = __ldg(xp + j);
            float dx = q.x - xv.x, dy = q.y - xv.y;
            float dz = q.z - xv.z, dw = q.w - xv.w;
            float4 o;
            o.x = xv.x + dx; o.y = xv.y + dy;
            o.z = xv.z + dz; o.w = xv.w + dw;
            op[j] = o;
            wsum += dx*dx + dy*dy + dz*dz + dw*dw;
        }
        if (lane == 0) atomicAdd(&counts_g[idx], 1u);
    }
    #pragma unroll
    for (int o = 16; o; o >>= 1) wsum += __shfl_xor_sync(0xffffffffu, wsum, o);
    if (lane == 0) atomicAdd(&loss_g, (double)wsum);
}

// ---------------------------------------------------------------------------
__global__ void vq_finalize(float* __restrict__ out, long long ME, int M, int N,
                            int write_scalars) {
    __shared__ float red[32];
    int tid = threadIdx.x;
    float v = 0.0f;
    if (tid < N) {
        float p = (float)counts_g[tid] / (float)M;
        v = p * logf(p + 1e-10f);
    }
    #pragma unroll
    for (int o = 16; o; o >>= 1) v += __shfl_xor_sync(0xffffffffu, v, o);
    if ((tid & 31) == 0) red[tid >> 5] = v;
    __syncthreads();
    if (tid < 32) {
        float s = (tid < ((int)blockDim.x >> 5)) ? red[tid] : 0.0f;
        #pragma unroll
        for (int o = 16; o; o >>= 1) s += __shfl_xor_sync(0xffffffffu, s, o);
        if (tid == 0 && write_scalars) {
            float perp = expf(-s);
            float m = (float)(loss_g / (double)ME);
            out[ME]     = m + 0.25f * m;
            out[ME + 1] = perp;
        }
    }
}

// ---------------------------------------------------------------------------
extern "C" void kernel_launch(void* const* d_in, const int* in_sizes, int n_in,
                              void* d_out, int out_size) {
    const float* x   = (const float*)d_in[0];
    const float* emb = (const float*)d_in[1];
    float* out = (float*)d_out;

    int M = in_sizes[0] / K_DIM;   // 65536
    int N = in_sizes[1] / K_DIM;   // 1024

    cudaFuncSetAttribute(vq_main, cudaFuncAttributeMaxDynamicSharedMemorySize,
                         SMEM_TOTAL);

    vq_nop<<<1, 32>>>();   // pads launch count so ncu (-s 5) captures vq_main

    int prep_threads = N * 32;
    if (prep_threads < MAX_N) prep_threads = MAX_N;
    vq_prep<<<(prep_threads + 255) / 256, 256>>>(emb, N);

    vq_main<<<M / BM, 256, SMEM_TOTAL>>>(x, emb, out, M, N);

    long long ME = (long long)M * K_DIM;
    int ws = ((long long)out_size >= ME + 2) ? 1 : 0;
    vq_finalize<<<1, 1024>>>(out, ME, M, N, ws);
}